// round 10
// baseline (speedup 1.0000x reference)
#include <cuda_runtime.h>
#include <cuda_bf16.h>
#include <cstdint>

namespace {
constexpr int Sd = 2048, Dd = 64, QT = 64, CH = 64, NCH = Sd / CH, NT = 256;
constexpr int PIT = 72;                      // bf16 row pitch (conflict-free LDSM)
constexpr int TILE = QT * PIT * 2;           // 9216 bytes per bf16 tile

// K_a smem: Q hi/lo + K 2bufs x (hi+lo)
constexpr int A_SQH = 0, A_SQL = TILE, A_SK = 2 * TILE;
constexpr int A_SMEM = 6 * TILE;             // 55296

// K_b smem: P 2bufs x (hi+lo) + V 2bufs x (hi+lo) + sinv[64]
constexpr int B_SP = 0, B_SV = 4 * TILE, B_SINV = 8 * TILE;
constexpr int B_SMEM = 8 * TILE + 256;       // 73984

__device__ float g_inv[65536];

__device__ __forceinline__ uint32_t smem_u32(const void* p) {
    uint32_t a;
    asm("{ .reg .u64 t; cvta.to.shared.u64 t, %1; cvt.u32.u64 %0, t; }"
        : "=r"(a) : "l"(p));
    return a;
}
__device__ __forceinline__ uint32_t pack2(float a, float b) {  // lo=a, hi=b
    uint32_t r;
    asm("cvt.rn.bf16x2.f32 %0, %1, %2;" : "=r"(r) : "f"(b), "f"(a));
    return r;
}
__device__ __forceinline__ float bfr(float x) {
    return __bfloat162float(__float2bfloat16(x));
}
__device__ __forceinline__ void ldm_x4(uint32_t a, uint32_t* r) {
    asm volatile("ldmatrix.sync.aligned.m8n8.x4.shared.b16 {%0,%1,%2,%3}, [%4];"
                 : "=r"(r[0]), "=r"(r[1]), "=r"(r[2]), "=r"(r[3]) : "r"(a));
}
__device__ __forceinline__ void ldm_x2(uint32_t a, uint32_t* r) {
    asm volatile("ldmatrix.sync.aligned.m8n8.x2.shared.b16 {%0,%1}, [%2];"
                 : "=r"(r[0]), "=r"(r[1]) : "r"(a));
}
__device__ __forceinline__ void ldm_x2t(uint32_t a, uint32_t* r) {
    asm volatile("ldmatrix.sync.aligned.m8n8.x2.trans.shared.b16 {%0,%1}, [%2];"
                 : "=r"(r[0]), "=r"(r[1]) : "r"(a));
}
__device__ __forceinline__ void mma_bf16(float* d, const uint32_t* a,
                                         const uint32_t* b) {
    asm volatile(
        "mma.sync.aligned.m16n8k16.row.col.f32.bf16.bf16.f32 "
        "{%0,%1,%2,%3}, {%4,%5,%6,%7}, {%8,%9}, {%0,%1,%2,%3};"
        : "+f"(d[0]), "+f"(d[1]), "+f"(d[2]), "+f"(d[3])
        : "r"(a[0]), "r"(a[1]), "r"(a[2]), "r"(a[3]), "r"(b[0]), "r"(b[1]));
}

// [64 x 64] fp32 -> bf16 hi/lo tiles, pitch-72 rows. 256 threads.
__device__ __forceinline__ void load_conv(const float* __restrict__ src,
                                          char* sm, int offH, int offL,
                                          int t, float scale) {
    #pragma unroll
    for (int i = 0; i < 4; ++i) {
        const int idx4 = t + NT * i;
        const int row = idx4 >> 4, c4 = (idx4 & 15) << 2;
        float4 v = *(const float4*)(src + (size_t)idx4 * 4);
        v.x *= scale; v.y *= scale; v.z *= scale; v.w *= scale;
        const float hx = bfr(v.x), hy = bfr(v.y), hz = bfr(v.z), hw = bfr(v.w);
        const int boff = (row * PIT + c4) * 2;
        *(uint2*)(sm + offH + boff) = make_uint2(pack2(v.x, v.y), pack2(v.z, v.w));
        *(uint2*)(sm + offL + boff) =
            make_uint2(pack2(v.x - hx, v.y - hy), pack2(v.z - hz, v.w - hw));
    }
}

// bf16 bits (u16) -> fp32
__device__ __forceinline__ float b2f(uint32_t hi_bits_in_low) {
    return __uint_as_float(hi_bits_in_low << 16);
}
} // namespace

// ============================ K_a: QK + exp ================================
__global__ void __launch_bounds__(NT, 2)
attn_qk_kernel(const float* __restrict__ Q, const float* __restrict__ K,
               const float* __restrict__ Mk, uint32_t* __restrict__ AT)
{
    extern __shared__ char smem[];
    const uint32_t sb = smem_u32(smem);

    const int t = threadIdx.x, w = t >> 5, l = t & 31;
    const int qw = w & 3, kh = w >> 2;
    const int gid = l >> 2, qd = l & 3;
    const int qt = blockIdx.x, bh = blockIdx.y;

    const float* Qb = Q + ((long)bh * Sd + qt * QT) * Dd;
    const float* Kb = K + (long)bh * Sd * Dd;
    const float* Mb = Mk + ((long)bh * Sd + qt * QT) * Sd;
    uint32_t*    Ab = AT + ((long)bh * Sd + qt * QT) * Sd;

    load_conv(Qb, smem, A_SQH, A_SQL, t, 0.125f);
    load_conv(Kb, smem, A_SK, A_SK + TILE, t, 1.0f);
    __syncthreads();

    uint32_t qh[4][4], ql[4][4];
    {
        const int rowb = ((16 * qw + (l & 15)) * PIT + ((l >> 4) << 3)) * 2;
        #pragma unroll
        for (int kt = 0; kt < 4; ++kt) {
            ldm_x4(sb + A_SQH + rowb + kt * 32, qh[kt]);
            ldm_x4(sb + A_SQL + rowb + kt * 32, ql[kt]);
        }
    }

    float rs0 = 0.f, rs1 = 0.f;
    const int l2 = l & 15;
    const int koff = ((l2 & 7) * PIT + ((l2 >> 3) << 3)) * 2;
    const float* mrow = Mb + (long)(16 * qw + gid) * Sd + kh * 32 + 2 * qd;
    uint32_t*    arow = Ab + (long)(16 * qw + gid) * Sd + kh * 32 + 2 * qd;

    for (int c = 0; c < NCH; ++c) {
        const int buf = c & 1;
        if (c + 1 < NCH)
            load_conv(Kb + (long)(c + 1) * CH * Dd, smem,
                      A_SK + (buf ^ 1) * 2 * TILE,
                      A_SK + (buf ^ 1) * 2 * TILE + TILE, t, 1.0f);

        const uint32_t kh_base = sb + A_SK + buf * 2 * TILE + koff;
        const uint32_t kl_base = kh_base + TILE;
        const int cb = c * CH;

        #pragma unroll
        for (int nt = 0; nt < 4; ++nt) {
            const int ntg = kh * 4 + nt;
            float sA[4] = {0.f,0.f,0.f,0.f};
            float sB[4] = {0.f,0.f,0.f,0.f};
            float sC[4] = {0.f,0.f,0.f,0.f};
            #pragma unroll
            for (int kt = 0; kt < 4; ++kt) {
                const uint32_t off = (uint32_t)(ntg * 8 * PIT * 2 + kt * 32);
                uint32_t kfh[2], kfl[2];
                ldm_x2(kh_base + off, kfh);
                ldm_x2(kl_base + off, kfl);
                mma_bf16(sA, qh[kt], kfh);
                mma_bf16(sB, qh[kt], kfl);
                mma_bf16(sC, ql[kt], kfh);
            }
            const float2 m0 = *(const float2*)(mrow + cb + nt * 8);
            const float2 m1 = *(const float2*)(mrow + cb + nt * 8 + 8 * (long)Sd);
            const float e0 = __expf((sA[0] + sB[0]) + (sC[0] + m0.x));
            const float e1 = __expf((sA[1] + sB[1]) + (sC[1] + m0.y));
            const float e2 = __expf((sA[2] + sB[2]) + (sC[2] + m1.x));
            const float e3 = __expf((sA[3] + sB[3]) + (sC[3] + m1.y));
            rs0 += e0 + e1; rs1 += e2 + e3;
            // packed: low16 = bf16 hi, high16 = bf16 lo
            const uint32_t u0 = pack2(e0, e0 - bfr(e0));
            const uint32_t u1 = pack2(e1, e1 - bfr(e1));
            const uint32_t u2 = pack2(e2, e2 - bfr(e2));
            const uint32_t u3 = pack2(e3, e3 - bfr(e3));
            *(uint2*)(arow + cb + nt * 8) = make_uint2(u0, u1);
            *(uint2*)(arow + cb + nt * 8 + 8 * (long)Sd) = make_uint2(u2, u3);
        }
        __syncthreads();
    }

    #pragma unroll
    for (int o = 1; o < 4; o <<= 1) {
        rs0 += __shfl_xor_sync(0xffffffffu, rs0, o);
        rs1 += __shfl_xor_sync(0xffffffffu, rs1, o);
    }
    float* srs = (float*)smem;            // [2][64] (Q region dead)
    if (qd == 0) {
        srs[kh * 64 + 16 * qw + gid]     = rs0;
        srs[kh * 64 + 16 * qw + gid + 8] = rs1;
    }
    __syncthreads();
    if (qd == 0 && kh == 0) {
        const int r0 = 16 * qw + gid;
        const int grow = bh * Sd + qt * QT + r0;
        g_inv[grow]     = 1.0f / (srs[r0] + srs[64 + r0]);
        g_inv[grow + 8] = 1.0f / (srs[r0 + 8] + srs[64 + r0 + 8]);
    }
}

// ====================== K_b: normalize attn + PV ============================
__global__ void __launch_bounds__(NT, 2)
attn_pv_kernel(const float* __restrict__ V, float* __restrict__ OC,
               float* __restrict__ OA)
{
    extern __shared__ char smem[];
    const uint32_t sb = smem_u32(smem);
    float* sinv = (float*)(smem + B_SINV);

    const int t = threadIdx.x, w = t >> 5, l = t & 31;
    const int qw = w & 3, kh = w >> 2;
    const int gid = l >> 2, qd = l & 3;
    const int qt = blockIdx.x, bh = blockIdx.y;

    const float* Vb = V + (long)bh * Sd * Dd;
    float*       Ab = OA + ((long)bh * Sd + qt * QT) * Sd;
    uint32_t*    Au = (uint32_t*)Ab;
    float*       Cb = OC + ((long)bh * Sd + qt * QT) * Dd;

    if (t < 64) sinv[t] = g_inv[bh * Sd + qt * QT + t];
    __syncthreads();

    // Stage packed P chunk c: write normalized fp32 attn + fill hi/lo tiles.
    auto stage_p = [&](int c, int pbase) {
        const int cb = c * CH;
        #pragma unroll
        for (int i = 0; i < 4; ++i) {
            const int idx4 = t + NT * i;
            const int row = idx4 >> 4, colu = (idx4 & 15) << 2;
            const long g = (long)row * Sd + cb + colu;
            const uint4 u = *(const uint4*)(Au + g);
            const float inv = sinv[row];
            const float e0 = b2f(u.x & 0xffffu) + __uint_as_float(u.x & 0xffff0000u);
            const float e1 = b2f(u.y & 0xffffu) + __uint_as_float(u.y & 0xffff0000u);
            const float e2 = b2f(u.z & 0xffffu) + __uint_as_float(u.z & 0xffff0000u);
            const float e3 = b2f(u.w & 0xffffu) + __uint_as_float(u.w & 0xffff0000u);
            *(float4*)(Ab + g) =
                make_float4(e0 * inv, e1 * inv, e2 * inv, e3 * inv);
            const uint32_t hi01 = __byte_perm(u.x, u.y, 0x5410);
            const uint32_t hi23 = __byte_perm(u.z, u.w, 0x5410);
            const uint32_t lo01 = __byte_perm(u.x, u.y, 0x7632);
            const uint32_t lo23 = __byte_perm(u.z, u.w, 0x7632);
            const int boff = (row * PIT + colu) * 2;
            *(uint2*)(smem + pbase + boff) = make_uint2(hi01, hi23);
            *(uint2*)(smem + pbase + TILE + boff) = make_uint2(lo01, lo23);
        }
    };

    stage_p(0, B_SP);
    load_conv(Vb, smem, B_SV, B_SV + TILE, t, 1.0f);
    __syncthreads();

    float ctx[8][4];
    #pragma unroll
    for (int d = 0; d < 8; ++d)
        { ctx[d][0] = 0.f; ctx[d][1] = 0.f; ctx[d][2] = 0.f; ctx[d][3] = 0.f; }

    const int l2 = l & 15;
    const int voff = (l2 * PIT) * 2;

    for (int c = 0; c < NCH; ++c) {
        const int buf = c & 1;
        if (c + 1 < NCH) {
            stage_p(c + 1, B_SP + (buf ^ 1) * 2 * TILE);
            load_conv(Vb + (long)(c + 1) * CH * Dd, smem,
                      B_SV + (buf ^ 1) * 2 * TILE,
                      B_SV + (buf ^ 1) * 2 * TILE + TILE, t, 1.0f);
        }

        const uint32_t p_base = sb + B_SP + buf * 2 * TILE;
        const uint32_t vh_base = sb + B_SV + buf * 2 * TILE + voff;
        const uint32_t vl_base = vh_base + TILE;

        #pragma unroll
        for (int kt = 0; kt < 2; ++kt) {
            const int ktg = kh * 2 + kt;
            uint32_t ah[4], al[4];
            const int rowb =
                ((16 * qw + (l & 15)) * PIT + ktg * 16 + ((l >> 4) << 3)) * 2;
            ldm_x4(p_base + rowb, ah);
            ldm_x4(p_base + TILE + rowb, al);
            const uint32_t vrow = (uint32_t)(ktg * 16 * PIT * 2);
            #pragma unroll
            for (int dt = 0; dt < 8; ++dt) {
                uint32_t vfh[2], vfl[2];
                ldm_x2t(vh_base + vrow + dt * 16, vfh);
                ldm_x2t(vl_base + vrow + dt * 16, vfl);
                mma_bf16(ctx[dt], ah, vfh);
                mma_bf16(ctx[dt], ah, vfl);
                mma_bf16(ctx[dt], al, vfh);
            }
        }
        __syncthreads();
    }

    const int r0 = 16 * qw + gid;
    const float inv0 = sinv[r0], inv1 = sinv[r0 + 8];

    float* cs = (float*)smem;             // 64 x 68 floats (P region dead)
    if (kh == 1) {
        #pragma unroll
        for (int dt = 0; dt < 8; ++dt) {
            *(float2*)(cs + r0 * 68 + dt * 8 + 2 * qd) =
                make_float2(ctx[dt][0], ctx[dt][1]);
            *(float2*)(cs + (r0 + 8) * 68 + dt * 8 + 2 * qd) =
                make_float2(ctx[dt][2], ctx[dt][3]);
        }
    }
    __syncthreads();
    if (kh == 0) {
        float* crow = Cb + (long)r0 * Dd + 2 * qd;
        #pragma unroll
        for (int dt = 0; dt < 8; ++dt) {
            const float2 p0 = *(const float2*)(cs + r0 * 68 + dt * 8 + 2 * qd);
            const float2 p1 = *(const float2*)(cs + (r0 + 8) * 68 + dt * 8 + 2 * qd);
            *(float2*)(crow + dt * 8) =
                make_float2((ctx[dt][0] + p0.x) * inv0, (ctx[dt][1] + p0.y) * inv0);
            *(float2*)(crow + dt * 8 + 8 * Dd) =
                make_float2((ctx[dt][2] + p1.x) * inv1, (ctx[dt][3] + p1.y) * inv1);
        }
    }
}

extern "C" void kernel_launch(void* const* d_in, const int* in_sizes, int n_in,
                              void* d_out, int out_size) {
    const float* Q = (const float*)d_in[0];
    const float* K = (const float*)d_in[1];
    const float* V = (const float*)d_in[2];
    const float* M = (const float*)d_in[3];

    float* ctx  = (float*)d_out;
    float* attn = (float*)d_out + (size_t)2 * 16 * 2048 * 64;

    cudaFuncSetAttribute(attn_qk_kernel,
                         cudaFuncAttributeMaxDynamicSharedMemorySize, A_SMEM);
    cudaFuncSetAttribute(attn_pv_kernel,
                         cudaFuncAttributeMaxDynamicSharedMemorySize, B_SMEM);

    dim3 grid(Sd / QT, 32);   // (32, 32)
    attn_qk_kernel<<<grid, NT, A_SMEM>>>(Q, K, M, (uint32_t*)attn);
    attn_pv_kernel<<<grid, NT, B_SMEM>>>(V, ctx, attn);
}

// round 11
// speedup vs baseline: 1.3242x; 1.3242x over previous
#include <cuda_runtime.h>
#include <cuda_bf16.h>
#include <cstdint>

namespace {
constexpr int Sd = 2048, Dd = 64, QT = 64, CH = 64, NCH = Sd / CH, NT = 256;
constexpr int PIT = 72;                      // bf16 row pitch (conflict-free LDSM)
constexpr int TILE = QT * PIT * 2;           // 9216 bytes per bf16 tile
constexpr int SQH = 0, SQL = TILE;           // Q hi/lo
constexpr int SK = 2 * TILE;                 // K: 2 bufs x (hi+lo)
constexpr int SV = SK + 4 * TILE;            // V: 2 bufs x (hi+lo)
constexpr int SMEM_BYTES = SV + 4 * TILE;    // 92160

__device__ float g_inv[65536];
// Pre-converted bf16 hi/lo copies of K and V (8 MB each).
__device__ __nv_bfloat16 g_KH[2 * 16 * 2048 * 64];
__device__ __nv_bfloat16 g_KL[2 * 16 * 2048 * 64];
__device__ __nv_bfloat16 g_VH[2 * 16 * 2048 * 64];
__device__ __nv_bfloat16 g_VL[2 * 16 * 2048 * 64];

__device__ __forceinline__ uint32_t smem_u32(const void* p) {
    uint32_t a;
    asm("{ .reg .u64 t; cvta.to.shared.u64 t, %1; cvt.u32.u64 %0, t; }"
        : "=r"(a) : "l"(p));
    return a;
}
__device__ __forceinline__ uint32_t pack2(float a, float b) {  // lo=a, hi=b
    uint32_t r;
    asm("cvt.rn.bf16x2.f32 %0, %1, %2;" : "=r"(r) : "f"(b), "f"(a));
    return r;
}
__device__ __forceinline__ float bfr(float x) {
    return __bfloat162float(__float2bfloat16(x));
}
__device__ __forceinline__ void ldm_x4(uint32_t a, uint32_t* r) {
    asm volatile("ldmatrix.sync.aligned.m8n8.x4.shared.b16 {%0,%1,%2,%3}, [%4];"
                 : "=r"(r[0]), "=r"(r[1]), "=r"(r[2]), "=r"(r[3]) : "r"(a));
}
__device__ __forceinline__ void ldm_x2(uint32_t a, uint32_t* r) {
    asm volatile("ldmatrix.sync.aligned.m8n8.x2.shared.b16 {%0,%1}, [%2];"
                 : "=r"(r[0]), "=r"(r[1]) : "r"(a));
}
__device__ __forceinline__ void ldm_x2t(uint32_t a, uint32_t* r) {
    asm volatile("ldmatrix.sync.aligned.m8n8.x2.trans.shared.b16 {%0,%1}, [%2];"
                 : "=r"(r[0]), "=r"(r[1]) : "r"(a));
}
__device__ __forceinline__ void mma_bf16(float* d, const uint32_t* a,
                                         const uint32_t* b) {
    asm volatile(
        "mma.sync.aligned.m16n8k16.row.col.f32.bf16.bf16.f32 "
        "{%0,%1,%2,%3}, {%4,%5,%6,%7}, {%8,%9}, {%0,%1,%2,%3};"
        : "+f"(d[0]), "+f"(d[1]), "+f"(d[2]), "+f"(d[3])
        : "r"(a[0]), "r"(a[1]), "r"(a[2]), "r"(a[3]), "r"(b[0]), "r"(b[1]));
}
__device__ __forceinline__ void cpa16(uint32_t dst, const void* src) {
    asm volatile("cp.async.cg.shared.global [%0], [%1], 16;"
                 :: "r"(dst), "l"(src));
}
__device__ __forceinline__ void cpa_commit() {
    asm volatile("cp.async.commit_group;" ::: "memory");
}
__device__ __forceinline__ void cpa_wait0() {
    asm volatile("cp.async.wait_group 0;" ::: "memory");
}

// Q: [64 x 64] fp32 -> bf16 hi/lo tiles, pitch-72 rows. 256 threads.
__device__ __forceinline__ void load_conv_q(const float* __restrict__ src,
                                            char* sm, int t) {
    #pragma unroll
    for (int i = 0; i < 4; ++i) {
        const int idx4 = t + NT * i;
        const int row = idx4 >> 4, c4 = (idx4 & 15) << 2;
        float4 v = *(const float4*)(src + (size_t)idx4 * 4);
        v.x *= 0.125f; v.y *= 0.125f; v.z *= 0.125f; v.w *= 0.125f;
        const float hx = bfr(v.x), hy = bfr(v.y), hz = bfr(v.z), hw = bfr(v.w);
        const int boff = (row * PIT + c4) * 2;
        *(uint2*)(sm + SQH + boff) = make_uint2(pack2(v.x, v.y), pack2(v.z, v.w));
        *(uint2*)(sm + SQL + boff) =
            make_uint2(pack2(v.x - hx, v.y - hy), pack2(v.z - hz, v.w - hw));
    }
}
} // namespace

// ---------------- prepass: fp32 K/V -> bf16 hi/lo scratch -------------------
__global__ void __launch_bounds__(256, 8)
conv_kv_kernel(const float* __restrict__ K, const float* __restrict__ V)
{
    const size_t i4 = (size_t)blockIdx.x * 256 + threadIdx.x;  // float4 index
    const float4 kv = *(const float4*)(K + i4 * 4);
    const float4 vv = *(const float4*)(V + i4 * 4);
    const float khx = bfr(kv.x), khy = bfr(kv.y), khz = bfr(kv.z), khw = bfr(kv.w);
    const float vhx = bfr(vv.x), vhy = bfr(vv.y), vhz = bfr(vv.z), vhw = bfr(vv.w);
    ((uint2*)g_KH)[i4] = make_uint2(pack2(kv.x, kv.y), pack2(kv.z, kv.w));
    ((uint2*)g_KL)[i4] =
        make_uint2(pack2(kv.x - khx, kv.y - khy), pack2(kv.z - khz, kv.w - khw));
    ((uint2*)g_VH)[i4] = make_uint2(pack2(vv.x, vv.y), pack2(vv.z, vv.w));
    ((uint2*)g_VL)[i4] =
        make_uint2(pack2(vv.x - vhx, vv.y - vhy), pack2(vv.z - vhz, vv.w - vhw));
}

// ---------------------------- main kernel -----------------------------------
__global__ void __launch_bounds__(NT, 2)
attn_mma_kernel(const float* __restrict__ Q, const float* __restrict__ Mk,
                float* __restrict__ OC, float* __restrict__ OA)
{
    extern __shared__ char smem[];
    const uint32_t sb = smem_u32(smem);

    const int t = threadIdx.x, w = t >> 5, l = t & 31;
    const int qw = w & 3, kh = w >> 2;
    const int gid = l >> 2, qd = l & 3;
    const int qt = blockIdx.x, bh = blockIdx.y;

    const float* Qb = Q + ((long)bh * Sd + qt * QT) * Dd;
    const float* Mb = Mk + ((long)bh * Sd + qt * QT) * Sd;
    float*       Ab = OA + ((long)bh * Sd + qt * QT) * Sd;
    float*       Cb = OC + ((long)bh * Sd + qt * QT) * Dd;

    const __nv_bfloat16* KHb = g_KH + (long)bh * Sd * Dd;
    const __nv_bfloat16* KLb = g_KL + (long)bh * Sd * Dd;
    const __nv_bfloat16* VHb = g_VH + (long)bh * Sd * Dd;
    const __nv_bfloat16* VLb = g_VL + (long)bh * Sd * Dd;

    // cp.async staging: thread t covers granules t and t+256 of each 8KB tile.
    // granule g: row r=g>>3, u=g&7; src byte off = (r*64 + u*8)*2; dst (r*PIT+u*8)*2.
    auto stage = [&](int c, int buf) {
        const long srow = (long)c * CH * Dd;
        const uint32_t kb = sb + SK + buf * 2 * TILE;
        const uint32_t vb = sb + SV + buf * 2 * TILE;
        #pragma unroll
        for (int half = 0; half < 2; ++half) {
            const int g = t + half * 256;
            const int r = g >> 3, u = g & 7;
            const long so = srow + r * Dd + u * 8;
            const uint32_t dofs = (uint32_t)((r * PIT + u * 8) * 2);
            cpa16(kb + dofs, KHb + so);
            cpa16(kb + TILE + dofs, KLb + so);
            cpa16(vb + dofs, VHb + so);
            cpa16(vb + TILE + dofs, VLb + so);
        }
    };

    stage(0, 0);
    cpa_commit();
    load_conv_q(Qb, smem, t);
    cpa_wait0();
    __syncthreads();

    uint32_t qh[4][4], ql[4][4];
    {
        const int rowb = ((16 * qw + (l & 15)) * PIT + ((l >> 4) << 3)) * 2;
        #pragma unroll
        for (int kt = 0; kt < 4; ++kt) {
            ldm_x4(sb + SQH + rowb + kt * 32, qh[kt]);
            ldm_x4(sb + SQL + rowb + kt * 32, ql[kt]);
        }
    }

    float ctx[8][4];
    #pragma unroll
    for (int d = 0; d < 8; ++d)
        { ctx[d][0] = 0.f; ctx[d][1] = 0.f; ctx[d][2] = 0.f; ctx[d][3] = 0.f; }
    float rs0 = 0.f, rs1 = 0.f;

    const int l2 = l & 15;
    const int koff = ((l2 & 7) * PIT + ((l2 >> 3) << 3)) * 2;
    const int voff = (l2 * PIT) * 2;

    const float* mrow = Mb + (long)(16 * qw + gid) * Sd + kh * 32 + 2 * qd;
    float*       arow = Ab + (long)(16 * qw + gid) * Sd + kh * 32 + 2 * qd;

    for (int c = 0; c < NCH; ++c) {
        const int buf = c & 1;
        if (c + 1 < NCH) { stage(c + 1, buf ^ 1); cpa_commit(); }

        // Prefetch this chunk's mask values (consumed ~1 QK phase later).
        const int cb = c * CH;
        float2 mk0[4], mk1[4];
        #pragma unroll
        for (int nt = 0; nt < 4; ++nt) {
            mk0[nt] = *(const float2*)(mrow + cb + nt * 8);
            mk1[nt] = *(const float2*)(mrow + cb + nt * 8 + 8 * (long)Sd);
        }

        const uint32_t kh_base = sb + SK + buf * 2 * TILE + koff;
        const uint32_t kl_base = kh_base + TILE;
        const uint32_t vh_base = sb + SV + buf * 2 * TILE + voff;
        const uint32_t vl_base = vh_base + TILE;

        uint32_t Ph[8], Pl[8];
        #pragma unroll
        for (int nt = 0; nt < 4; ++nt) {
            const int ntg = kh * 4 + nt;
            float sA[4] = {0.f,0.f,0.f,0.f};
            float sB[4] = {0.f,0.f,0.f,0.f};
            float sC[4] = {0.f,0.f,0.f,0.f};
            #pragma unroll
            for (int kt = 0; kt < 4; ++kt) {
                const uint32_t off = (uint32_t)(ntg * 8 * PIT * 2 + kt * 32);
                uint32_t kfh[2], kfl[2];
                ldm_x2(kh_base + off, kfh);
                ldm_x2(kl_base + off, kfl);
                mma_bf16(sA, qh[kt], kfh);
                mma_bf16(sB, qh[kt], kfl);
                mma_bf16(sC, ql[kt], kfh);
            }
            const float e0 = __expf((sA[0] + sB[0]) + (sC[0] + mk0[nt].x));
            const float e1 = __expf((sA[1] + sB[1]) + (sC[1] + mk0[nt].y));
            const float e2 = __expf((sA[2] + sB[2]) + (sC[2] + mk1[nt].x));
            const float e3 = __expf((sA[3] + sB[3]) + (sC[3] + mk1[nt].y));
            rs0 += e0 + e1; rs1 += e2 + e3;
            *(float2*)(arow + cb + nt * 8) = make_float2(e0, e1);
            *(float2*)(arow + cb + nt * 8 + 8 * (long)Sd) = make_float2(e2, e3);
            const float h0 = bfr(e0), h1 = bfr(e1), h2 = bfr(e2), h3 = bfr(e3);
            Ph[2 * nt]     = pack2(e0, e1);
            Ph[2 * nt + 1] = pack2(e2, e3);
            Pl[2 * nt]     = pack2(e0 - h0, e1 - h1);
            Pl[2 * nt + 1] = pack2(e2 - h2, e3 - h3);
        }

        #pragma unroll
        for (int kt = 0; kt < 2; ++kt) {
            const int ktg = kh * 2 + kt;
            const uint32_t* ah = Ph + 4 * kt;
            const uint32_t* al = Pl + 4 * kt;
            const uint32_t vrow = (uint32_t)(ktg * 16 * PIT * 2);
            #pragma unroll
            for (int dt = 0; dt < 8; ++dt) {
                uint32_t vfh[2], vfl[2];
                ldm_x2t(vh_base + vrow + dt * 16, vfh);
                ldm_x2t(vl_base + vrow + dt * 16, vfl);
                mma_bf16(ctx[dt], ah, vfh);
                mma_bf16(ctx[dt], ah, vfl);
                mma_bf16(ctx[dt], al, vfh);
            }
        }
        if (c + 1 < NCH) cpa_wait0();
        __syncthreads();
    }

    // rowsum: quad-reduce, then combine the two k-halves through smem.
    #pragma unroll
    for (int o = 1; o < 4; o <<= 1) {
        rs0 += __shfl_xor_sync(0xffffffffu, rs0, o);
        rs1 += __shfl_xor_sync(0xffffffffu, rs1, o);
    }
    float* srs = (float*)smem;            // [2][64]
    if (qd == 0) {
        srs[kh * 64 + 16 * qw + gid]     = rs0;
        srs[kh * 64 + 16 * qw + gid + 8] = rs1;
    }
    __syncthreads();
    const int r0 = 16 * qw + gid;
    const float inv0 = 1.0f / (srs[r0] + srs[64 + r0]);
    const float inv1 = 1.0f / (srs[r0 + 8] + srs[64 + r0 + 8]);
    if (qd == 0 && kh == 0) {
        const int grow = bh * Sd + qt * QT + r0;
        g_inv[grow]     = inv0;
        g_inv[grow + 8] = inv1;
    }

    // ctx: half 1 publishes partials (pitch-68), half 0 adds + stores.
    float* cs = (float*)(smem + 1024);    // 64 x 68 floats
    if (kh == 1) {
        #pragma unroll
        for (int dt = 0; dt < 8; ++dt) {
            *(float2*)(cs + r0 * 68 + dt * 8 + 2 * qd) =
                make_float2(ctx[dt][0], ctx[dt][1]);
            *(float2*)(cs + (r0 + 8) * 68 + dt * 8 + 2 * qd) =
                make_float2(ctx[dt][2], ctx[dt][3]);
        }
    }
    __syncthreads();
    if (kh == 0) {
        float* crow = Cb + (long)r0 * Dd + 2 * qd;
        #pragma unroll
        for (int dt = 0; dt < 8; ++dt) {
            const float2 p0 = *(const float2*)(cs + r0 * 68 + dt * 8 + 2 * qd);
            const float2 p1 = *(const float2*)(cs + (r0 + 8) * 68 + dt * 8 + 2 * qd);
            *(float2*)(crow + dt * 8) =
                make_float2((ctx[dt][0] + p0.x) * inv0, (ctx[dt][1] + p0.y) * inv0);
            *(float2*)(crow + dt * 8 + 8 * Dd) =
                make_float2((ctx[dt][2] + p1.x) * inv1, (ctx[dt][3] + p1.y) * inv1);
        }
    }
}

__global__ void __launch_bounds__(256, 8)
attn_norm_kernel(float* __restrict__ A)
{
    const size_t i = ((size_t)blockIdx.x * 256 + threadIdx.x) * 4;
    const int row = (int)(i >> 11);
    float4 v = *(float4*)(A + i);
    const float s = g_inv[row];
    v.x *= s; v.y *= s; v.z *= s; v.w *= s;
    *(float4*)(A + i) = v;
}

extern "C" void kernel_launch(void* const* d_in, const int* in_sizes, int n_in,
                              void* d_out, int out_size) {
    const float* Q = (const float*)d_in[0];
    const float* K = (const float*)d_in[1];
    const float* V = (const float*)d_in[2];
    const float* M = (const float*)d_in[3];

    float* ctx  = (float*)d_out;
    float* attn = (float*)d_out + (size_t)2 * 16 * 2048 * 64;

    cudaFuncSetAttribute(attn_mma_kernel,
                         cudaFuncAttributeMaxDynamicSharedMemorySize, SMEM_BYTES);

    // prepass: 2*16*2048*64 / 4 float4 per tensor = 1,048,576 threads
    conv_kv_kernel<<<4096, 256>>>(K, V);

    dim3 grid(Sd / QT, 32);   // (32, 32)
    attn_mma_kernel<<<grid, NT, SMEM_BYTES>>>(Q, M, ctx, attn);

    const size_t total4 = (size_t)32 * 2048 * 2048 / 4;
    attn_norm_kernel<<<(unsigned)(total4 / 256), 256>>>(attn);
}